// round 16
// baseline (speedup 1.0000x reference)
#include <cuda_runtime.h>
#include <cuda_fp16.h>
#include <cstdint>

// Problem constants
#define T_TOK 16384
#define H_DIM 1024
#define E_NUM 16
#define F_DIM 2048
#define K_TOP 2
#define TK    (T_TOK * K_TOP)   // 32768
#define N1    (2 * F_DIM)       // 4096
#define BM 128
#define BN 128
#define KC 32
#define MAX_TILES (TK / BM + E_NUM)

// smem (half units), 3-stage pipeline
#define ASTR  40                        // 32 + 8 pad halfs (80B rows, LDSM conflict-free)
#define BSTR  136                       // 128 + 8 pad halfs (272B rows, LDSM.T conflict-free)
#define ABUF  (BM * ASTR)               // 5120 halfs / stage
#define BBUF  (KC * BSTR)               // 4352 halfs / stage
#define AOFF  512                       // bytes (after 128 slot ints)
#define BOFF  (AOFF + 3 * ABUF * 2)     // 31232
#define SMEM_BYTES (BOFF + 3 * BBUF * 2)  // 57344 B -> 2 CTAs/SM

// -------- device scratch (allocation-free contract) --------
__device__ int    g_counts[E_NUM];
__device__ int    g_slots[E_NUM * TK];
__device__ int    g_numTiles;
__device__ int    g_tileE[MAX_TILES + 8];
__device__ int    g_tileRow[MAX_TILES + 8];
__device__ __half g_interh[(size_t)TK * F_DIM];          // 128 MB
__device__ __half g_w1h[(size_t)E_NUM * H_DIM * N1];     // 128 MB, native [E][H][N1] fp16
__device__ __half g_w2h[(size_t)E_NUM * F_DIM * H_DIM];  // 64 MB,  native [E][F][H] fp16
__device__ __half g_hidh[(size_t)T_TOK * H_DIM];         // 32 MB

// -------- helpers --------
__device__ __forceinline__ uint32_t smem_u32(const void* p) {
    uint32_t a;
    asm("{ .reg .u64 t; cvta.to.shared.u64 t, %1; cvt.u32.u64 %0, t; }" : "=r"(a) : "l"(p));
    return a;
}
__device__ __forceinline__ void cp16(uint32_t dst, const __half* src) {
    asm volatile("cp.async.ca.shared.global [%0], [%1], 16;" :: "r"(dst), "l"(src) : "memory");
}
#define CP_COMMIT() asm volatile("cp.async.commit_group;" ::: "memory")
#define CP_WAIT(n)  asm volatile("cp.async.wait_group %0;" :: "n"(n) : "memory")

__device__ __forceinline__ void ldsm4(uint32_t r[4], uint32_t a) {
    asm volatile("ldmatrix.sync.aligned.m8n8.x4.shared.b16 {%0,%1,%2,%3}, [%4];"
        : "=r"(r[0]), "=r"(r[1]), "=r"(r[2]), "=r"(r[3]) : "r"(a));
}
__device__ __forceinline__ void ldsm4t(uint32_t r[4], uint32_t a) {
    asm volatile("ldmatrix.sync.aligned.m8n8.x4.trans.shared.b16 {%0,%1,%2,%3}, [%4];"
        : "=r"(r[0]), "=r"(r[1]), "=r"(r[2]), "=r"(r[3]) : "r"(a));
}
__device__ __forceinline__ void mma16(float c[4], const uint32_t a[4], const uint32_t b[2]) {
    asm volatile(
        "mma.sync.aligned.m16n8k16.row.col.f32.f16.f16.f32 "
        "{%0,%1,%2,%3}, {%4,%5,%6,%7}, {%8,%9}, {%0,%1,%2,%3};"
        : "+f"(c[0]), "+f"(c[1]), "+f"(c[2]), "+f"(c[3])
        : "r"(a[0]), "r"(a[1]), "r"(a[2]), "r"(a[3]), "r"(b[0]), "r"(b[1]));
}

// warp tile 64x64 (mt 0..3 x 8 n8-tiles). One KC=32 chunk = 2 k16 steps.
// aA[4]: per-mt LDSM lane addrs; bA[4]: per-n16 LDSM.T lane addrs (stage-relative).
__device__ __forceinline__ void compute_chunk(
    uint32_t aBase, uint32_t bBase, float c[4][8][4],
    const uint32_t aA[4], const uint32_t bA[4])
{
    #pragma unroll
    for (int kk = 0; kk < 2; kk++) {
        uint32_t af[4][4], bf[4][4];
        #pragma unroll
        for (int mt = 0; mt < 4; mt++)
            ldsm4(af[mt], aBase + aA[mt] + kk * 32);              // +16 halfs in K
        #pragma unroll
        for (int p = 0; p < 4; p++)
            ldsm4t(bf[p], bBase + bA[p] + kk * 16 * BSTR * 2);    // +16 K-rows
        #pragma unroll
        for (int mt = 0; mt < 4; mt++)
            #pragma unroll
            for (int p = 0; p < 4; p++) {
                mma16(c[mt][2 * p],     af[mt], &bf[p][0]);       // n = wn+p*16
                mma16(c[mt][2 * p + 1], af[mt], &bf[p][2]);       // n = wn+p*16+8
            }
    }
}

// -------- setup kernels --------
__global__ void k_init(float* __restrict__ out) {
    int i = blockIdx.x * blockDim.x + threadIdx.x;
    if (i < T_TOK * H_DIM) out[i] = 0.0f;
    if (i < E_NUM) g_counts[i] = 0;
}
__global__ void k_build(const int* __restrict__ topk_ids) {
    int i = blockIdx.x * blockDim.x + threadIdx.x;
    if (i < TK) {
        int e = topk_ids[i];
        int pos = atomicAdd(&g_counts[e], 1);
        g_slots[e * TK + pos] = i;
    }
}
__global__ void k_tilemap() {
    if (threadIdx.x == 0 && blockIdx.x == 0) {
        int idx = 0;
        for (int e = 0; e < E_NUM; e++) {
            int c = g_counts[e];
            for (int r = 0; r < c; r += BM) { g_tileE[idx] = e; g_tileRow[idx] = r; idx++; }
        }
        g_numTiles = idx;
    }
}
// fp32 -> fp16 elementwise
__global__ void k_cvt(const float* __restrict__ s, __half* __restrict__ d, int n4) {
    int i = blockIdx.x * blockDim.x + threadIdx.x;
    if (i < n4) {
        float4 v = ((const float4*)s)[i];
        __half2 h0 = __floats2half2_rn(v.x, v.y);
        __half2 h1 = __floats2half2_rn(v.z, v.w);
        uint2 u = make_uint2(*(uint32_t*)&h0, *(uint32_t*)&h1);
        ((uint2*)d)[i] = u;
    }
}

// ================= GEMM1: hidden @ W1[e] + b1, swiglu -> g_interh =================
__global__ void __launch_bounds__(128, 2) k_gemm1(const float* __restrict__ bias)
{
    extern __shared__ char smem[];
    int tileIdx = blockIdx.y;
    if (tileIdx >= g_numTiles) return;
    int e = g_tileE[tileIdx], rowStart = g_tileRow[tileIdx];
    int rowsHere = min(BM, g_counts[e] - rowStart);
    int n0 = blockIdx.x * BN;
    int tid = threadIdx.x;

    int* sSlot = (int*)smem;
    sSlot[tid] = (tid < rowsHere) ? g_slots[e * TK + rowStart + tid]
                                  : g_slots[e * TK + rowStart];
    __syncthreads();

    // A loaders: rows aldr, aldr+64; 16 halfs each at asp
    int aldr = tid >> 1, asp = (tid & 1) * 16;
    const __half* aS0 = g_hidh + (size_t)(sSlot[aldr]      >> 1) * H_DIM + asp;
    const __half* aS1 = g_hidh + (size_t)(sSlot[aldr + 64] >> 1) * H_DIM + asp;
    // B loaders: k-rows bldr, bldr+16; 16 halfs each at bcol
    int bldr = tid >> 3, bcol = (tid & 7) * 16;
    const __half* bSrc = g_w1h + (size_t)e * H_DIM * N1 + (size_t)bldr * N1 + n0 + bcol;

    uint32_t smU = smem_u32(smem);
    uint32_t aD = smU + AOFF + (aldr * ASTR + asp) * 2;
    uint32_t bD = smU + BOFF + (bldr * BSTR + bcol) * 2;

    int lane = tid & 31, g_ = lane >> 2, tq = lane & 3;
    int wid = tid >> 5;
    int wm = (wid & 1) * 64, wn = (wid >> 1) * 64;

    // LDSM lane addressing
    int lt = lane >> 3, lrw = lane & 7;
    uint32_t aA[4], bA[4];
    #pragma unroll
    for (int mt = 0; mt < 4; mt++)
        aA[mt] = ((wm + mt * 16 + (lt & 1) * 8 + lrw) * ASTR + (lt >> 1) * 8) * 2;
    #pragma unroll
    for (int p = 0; p < 4; p++)
        bA[p] = (((lt & 1) * 8 + lrw) * BSTR + wn + p * 16 + (lt >> 1) * 8) * 2;

    float c[4][8][4];
    #pragma unroll
    for (int i = 0; i < 4; i++)
        #pragma unroll
        for (int j = 0; j < 8; j++)
            #pragma unroll
            for (int q = 0; q < 4; q++) c[i][j][q] = 0.0f;

#define ISSUE1(CH, ST) do {                                  \
    int k0 = (CH) * KC;                                      \
    uint32_t ad = aD + (ST) * (ABUF * 2);                    \
    cp16(ad,                 aS0 + k0);                      \
    cp16(ad + 16,            aS0 + k0 + 8);                  \
    cp16(ad + 64 * ASTR * 2,      aS1 + k0);                 \
    cp16(ad + 64 * ASTR * 2 + 16, aS1 + k0 + 8);             \
    uint32_t bd = bD + (ST) * (BBUF * 2);                    \
    const __half* bs = bSrc + (size_t)k0 * N1;               \
    cp16(bd,                 bs);                            \
    cp16(bd + 16,            bs + 8);                        \
    cp16(bd + 16 * BSTR * 2,      bs + (size_t)16 * N1);     \
    cp16(bd + 16 * BSTR * 2 + 16, bs + (size_t)16 * N1 + 8); } while (0)

    const int NC = H_DIM / KC;   // 32
    ISSUE1(0, 0); CP_COMMIT();
    ISSUE1(1, 1); CP_COMMIT();

    for (int ch = 0; ch < NC; ch++) {
        int st = ch % 3;
        if (ch + 2 < NC) { ISSUE1(ch + 2, (ch + 2) % 3); CP_COMMIT(); CP_WAIT(2); }
        else if (ch + 1 < NC) { CP_WAIT(1); }
        else { CP_WAIT(0); }
        __syncthreads();
        compute_chunk(smU + AOFF + st * (ABUF * 2), smU + BOFF + st * (BBUF * 2),
                      c, aA, bA);
        __syncthreads();
    }
#undef ISSUE1

    // epilogue: bias + swiglu, store fp16 to g_interh
    const float* bp = bias + (size_t)e * N1 + n0;
    #pragma unroll
    for (int mt = 0; mt < 4; mt++) {
        #pragma unroll
        for (int half = 0; half < 2; half++) {
            int r = wm + mt * 16 + g_ + half * 8;
            if (r < rowsHere) {
                int slot = sSlot[r];
                __half* orow = g_interh + (size_t)slot * F_DIM + (n0 >> 1) + (wn >> 1);
                #pragma unroll
                for (int nt = 0; nt < 8; nt++) {
                    int cb = wn + nt * 8 + 2 * tq;
                    float gt = c[mt][nt][half * 2 + 0] + bp[cb];
                    float up = c[mt][nt][half * 2 + 1] + bp[cb + 1];
                    gt = fminf(gt, 7.0f);
                    up = fminf(fmaxf(up, -7.0f), 7.0f);
                    float glu = gt / (1.0f + __expf(-1.702f * gt));
                    orow[nt * 4 + tq] = __float2half_rn((up + 1.0f) * glu);
                }
            }
        }
    }
}

// ================= GEMM2: g_interh @ W2[e] + b2, weighted atomic combine =================
__global__ void __launch_bounds__(128, 2) k_gemm2(
    const float* __restrict__ bias, const float* __restrict__ tw,
    float* __restrict__ out)
{
    extern __shared__ char smem[];
    int tileIdx = blockIdx.y;
    if (tileIdx >= g_numTiles) return;
    int e = g_tileE[tileIdx], rowStart = g_tileRow[tileIdx];
    int rowsHere = min(BM, g_counts[e] - rowStart);
    int n0 = blockIdx.x * BN;
    int tid = threadIdx.x;

    int* sSlot = (int*)smem;
    sSlot[tid] = (tid < rowsHere) ? g_slots[e * TK + rowStart + tid]
                                  : g_slots[e * TK + rowStart];
    __syncthreads();

    int aldr = tid >> 1, asp = (tid & 1) * 16;
    const __half* aS0 = g_interh + (size_t)sSlot[aldr]      * F_DIM + asp;
    const __half* aS1 = g_interh + (size_t)sSlot[aldr + 64] * F_DIM + asp;
    int bldr = tid >> 3, bcol = (tid & 7) * 16;
    const __half* bSrc = g_w2h + (size_t)e * F_DIM * H_DIM + (size_t)bldr * H_DIM + n0 + bcol;

    uint32_t smU = smem_u32(smem);
    uint32_t aD = smU + AOFF + (aldr * ASTR + asp) * 2;
    uint32_t bD = smU + BOFF + (bldr * BSTR + bcol) * 2;

    int lane = tid & 31, g_ = lane >> 2, tq = lane & 3;
    int wid = tid >> 5;
    int wm = (wid & 1) * 64, wn = (wid >> 1) * 64;

    int lt = lane >> 3, lrw = lane & 7;
    uint32_t aA[4], bA[4];
    #pragma unroll
    for (int mt = 0; mt < 4; mt++)
        aA[mt] = ((wm + mt * 16 + (lt & 1) * 8 + lrw) * ASTR + (lt >> 1) * 8) * 2;
    #pragma unroll
    for (int p = 0; p < 4; p++)
        bA[p] = (((lt & 1) * 8 + lrw) * BSTR + wn + p * 16 + (lt >> 1) * 8) * 2;

    float c[4][8][4];
    #pragma unroll
    for (int i = 0; i < 4; i++)
        #pragma unroll
        for (int j = 0; j < 8; j++)
            #pragma unroll
            for (int q = 0; q < 4; q++) c[i][j][q] = 0.0f;

#define ISSUE2(CH, ST) do {                                  \
    int k0 = (CH) * KC;                                      \
    uint32_t ad = aD + (ST) * (ABUF * 2);                    \
    cp16(ad,                 aS0 + k0);                      \
    cp16(ad + 16,            aS0 + k0 + 8);                  \
    cp16(ad + 64 * ASTR * 2,      aS1 + k0);                 \
    cp16(ad + 64 * ASTR * 2 + 16, aS1 + k0 + 8);             \
    uint32_t bd = bD + (ST) * (BBUF * 2);                    \
    const __half* bs = bSrc + (size_t)k0 * H_DIM;            \
    cp16(bd,                 bs);                            \
    cp16(bd + 16,            bs + 8);                        \
    cp16(bd + 16 * BSTR * 2,      bs + (size_t)16 * H_DIM);  \
    cp16(bd + 16 * BSTR * 2 + 16, bs + (size_t)16 * H_DIM + 8); } while (0)

    const int NC = F_DIM / KC;   // 64
    ISSUE2(0, 0); CP_COMMIT();
    ISSUE2(1, 1); CP_COMMIT();

    for (int ch = 0; ch < NC; ch++) {
        int st = ch % 3;
        if (ch + 2 < NC) { ISSUE2(ch + 2, (ch + 2) % 3); CP_COMMIT(); CP_WAIT(2); }
        else if (ch + 1 < NC) { CP_WAIT(1); }
        else { CP_WAIT(0); }
        __syncthreads();
        compute_chunk(smU + AOFF + st * (ABUF * 2), smU + BOFF + st * (BBUF * 2),
                      c, aA, bA);
        __syncthreads();
    }
#undef ISSUE2

    // epilogue: bias, routing weight, atomic combine
    const float* bp = bias + (size_t)e * H_DIM + n0;
    #pragma unroll
    for (int mt = 0; mt < 4; mt++) {
        #pragma unroll
        for (int half = 0; half < 2; half++) {
            int r = wm + mt * 16 + g_ + half * 8;
            if (r < rowsHere) {
                int slot = sSlot[r];
                float w = tw[slot];
                float* orow = out + (size_t)(slot >> 1) * H_DIM + n0 + wn;
                #pragma unroll
                for (int nt = 0; nt < 8; nt++) {
                    int cb = nt * 8 + 2 * tq;
                    atomicAdd(orow + cb,     w * (c[mt][nt][half * 2 + 0] + bp[wn + cb]));
                    atomicAdd(orow + cb + 1, w * (c[mt][nt][half * 2 + 1] + bp[wn + cb + 1]));
                }
            }
        }
    }
}

extern "C" void kernel_launch(void* const* d_in, const int* in_sizes, int n_in,
                              void* d_out, int out_size) {
    const float* hidden = (const float*)d_in[0];   // [T, H]
    const float* tw     = (const float*)d_in[1];   // [T, K]
    const int*   ids    = (const int*)d_in[2];     // [T, K]
    const float* w1     = (const float*)d_in[3];   // [E, H, 2F]
    const float* b1     = (const float*)d_in[4];   // [E, 2F]
    const float* w2     = (const float*)d_in[5];   // [E, F, H]
    const float* b2     = (const float*)d_in[6];   // [E, H]
    float* out = (float*)d_out;                    // [T, H]

    cudaFuncSetAttribute(k_gemm1, cudaFuncAttributeMaxDynamicSharedMemorySize, SMEM_BYTES);
    cudaFuncSetAttribute(k_gemm2, cudaFuncAttributeMaxDynamicSharedMemorySize, SMEM_BYTES);

    __half* d_w1h;  cudaGetSymbolAddress((void**)&d_w1h, g_w1h);
    __half* d_w2h;  cudaGetSymbolAddress((void**)&d_w2h, g_w2h);
    __half* d_hidh; cudaGetSymbolAddress((void**)&d_hidh, g_hidh);

    int n = T_TOK * H_DIM;
    k_init<<<(n + 255) / 256, 256>>>(out);
    k_build<<<(TK + 255) / 256, 256>>>(ids);
    k_tilemap<<<1, 32>>>();
    // fp32 -> fp16 converts (ldmatrix.trans consumes B in native layout)
    k_cvt<<<(E_NUM * H_DIM * N1 / 4 + 255) / 256, 256>>>(w1, d_w1h, E_NUM * H_DIM * N1 / 4);
    k_cvt<<<(E_NUM * F_DIM * H_DIM / 4 + 255) / 256, 256>>>(w2, d_w2h, E_NUM * F_DIM * H_DIM / 4);
    k_cvt<<<(T_TOK * H_DIM / 4 + 255) / 256, 256>>>(hidden, d_hidh, T_TOK * H_DIM / 4);

    k_gemm1<<<dim3(N1 / BN, MAX_TILES), 128, SMEM_BYTES>>>(b1);
    k_gemm2<<<dim3(H_DIM / BN, MAX_TILES), 128, SMEM_BYTES>>>(b2, tw, out);
}

// round 17
// speedup vs baseline: 1.0802x; 1.0802x over previous
#include <cuda_runtime.h>
#include <cuda_fp16.h>
#include <cstdint>

// Problem constants
#define T_TOK 16384
#define H_DIM 1024
#define E_NUM 16
#define F_DIM 2048
#define K_TOP 2
#define TK    (T_TOK * K_TOP)   // 32768
#define N1    (2 * F_DIM)       // 4096
#define BM 128
#define BN 128
#define KC 32
#define MAX_TILES (TK / BM + E_NUM)

// smem (half units), 4-stage pipeline (single barrier per chunk)
#define ASTR  40                        // 32 + 8 pad halfs (80B rows, LDSM conflict-free)
#define BSTR  136                       // 128 + 8 pad halfs (272B rows, LDSM.T conflict-free)
#define ABUF  (BM * ASTR)               // 5120 halfs / stage
#define BBUF  (KC * BSTR)               // 4352 halfs / stage
#define AOFF  512                       // bytes (after 128 slot ints)
#define BOFF  (AOFF + 4 * ABUF * 2)     // 41472
#define SMEM_BYTES (BOFF + 4 * BBUF * 2)  // 76288 B -> 2 CTAs/SM (152.6 KB)

// -------- device scratch (allocation-free contract) --------
__device__ int    g_counts[E_NUM];
__device__ int    g_slots[E_NUM * TK];
__device__ int    g_numTiles;
__device__ int    g_tileE[MAX_TILES + 8];
__device__ int    g_tileRow[MAX_TILES + 8];
__device__ __half g_interh[(size_t)TK * F_DIM];          // 128 MB
__device__ __half g_w1h[(size_t)E_NUM * H_DIM * N1];     // 128 MB, native [E][H][N1] fp16
__device__ __half g_w2h[(size_t)E_NUM * F_DIM * H_DIM];  // 64 MB,  native [E][F][H] fp16
__device__ __half g_hidh[(size_t)T_TOK * H_DIM];         // 32 MB
__device__ float  g_out2[(size_t)TK * H_DIM];            // 128 MB per-slot GEMM2 output

// -------- helpers --------
__device__ __forceinline__ uint32_t smem_u32(const void* p) {
    uint32_t a;
    asm("{ .reg .u64 t; cvta.to.shared.u64 t, %1; cvt.u32.u64 %0, t; }" : "=r"(a) : "l"(p));
    return a;
}
__device__ __forceinline__ void cp16(uint32_t dst, const __half* src) {
    asm volatile("cp.async.ca.shared.global [%0], [%1], 16;" :: "r"(dst), "l"(src) : "memory");
}
#define CP_COMMIT() asm volatile("cp.async.commit_group;" ::: "memory")
#define CP_WAIT(n)  asm volatile("cp.async.wait_group %0;" :: "n"(n) : "memory")

__device__ __forceinline__ void ldsm4(uint32_t r[4], uint32_t a) {
    asm volatile("ldmatrix.sync.aligned.m8n8.x4.shared.b16 {%0,%1,%2,%3}, [%4];"
        : "=r"(r[0]), "=r"(r[1]), "=r"(r[2]), "=r"(r[3]) : "r"(a));
}
__device__ __forceinline__ void ldsm4t(uint32_t r[4], uint32_t a) {
    asm volatile("ldmatrix.sync.aligned.m8n8.x4.trans.shared.b16 {%0,%1,%2,%3}, [%4];"
        : "=r"(r[0]), "=r"(r[1]), "=r"(r[2]), "=r"(r[3]) : "r"(a));
}
__device__ __forceinline__ void mma16(float c[4], const uint32_t a[4], const uint32_t b[2]) {
    asm volatile(
        "mma.sync.aligned.m16n8k16.row.col.f32.f16.f16.f32 "
        "{%0,%1,%2,%3}, {%4,%5,%6,%7}, {%8,%9}, {%0,%1,%2,%3};"
        : "+f"(c[0]), "+f"(c[1]), "+f"(c[2]), "+f"(c[3])
        : "r"(a[0]), "r"(a[1]), "r"(a[2]), "r"(a[3]), "r"(b[0]), "r"(b[1]));
}

// warp tile 64x32. aA[4]: per-mt LDSM lane addrs (stage-relative bytes);
// bA[2]: per-n16-pair LDSM.T lane addrs. One KC=32 chunk = 2 k16 steps.
__device__ __forceinline__ void compute_chunk(
    uint32_t aBase, uint32_t bBase, float c[4][4][4],
    const uint32_t aA[4], const uint32_t bA[2])
{
    #pragma unroll
    for (int kk = 0; kk < 2; kk++) {
        uint32_t af[4][4], bf[2][4];
        #pragma unroll
        for (int mt = 0; mt < 4; mt++)
            ldsm4(af[mt], aBase + aA[mt] + kk * 32);              // +16 halfs in K
        #pragma unroll
        for (int p = 0; p < 2; p++)
            ldsm4t(bf[p], bBase + bA[p] + kk * 16 * BSTR * 2);    // +16 K-rows
        #pragma unroll
        for (int mt = 0; mt < 4; mt++)
            #pragma unroll
            for (int p = 0; p < 2; p++) {
                mma16(c[mt][2 * p],     af[mt], &bf[p][0]);       // n = wn+p*16
                mma16(c[mt][2 * p + 1], af[mt], &bf[p][2]);       // n = wn+p*16+8
            }
    }
}

// -------- setup kernels --------
__global__ void k_init() {
    if (threadIdx.x < E_NUM) g_counts[threadIdx.x] = 0;
}
__global__ void k_build(const int* __restrict__ topk_ids) {
    int i = blockIdx.x * blockDim.x + threadIdx.x;
    if (i < TK) {
        int e = topk_ids[i];
        int pos = atomicAdd(&g_counts[e], 1);
        g_slots[e * TK + pos] = i;
    }
}
__global__ void k_tilemap() {
    if (threadIdx.x == 0 && blockIdx.x == 0) {
        int idx = 0;
        for (int e = 0; e < E_NUM; e++) {
            int c = g_counts[e];
            for (int r = 0; r < c; r += BM) { g_tileE[idx] = e; g_tileRow[idx] = r; idx++; }
        }
        g_numTiles = idx;
    }
}
// fp32 -> fp16 elementwise
__global__ void k_cvt(const float* __restrict__ s, __half* __restrict__ d, int n4) {
    int i = blockIdx.x * blockDim.x + threadIdx.x;
    if (i < n4) {
        float4 v = ((const float4*)s)[i];
        __half2 h0 = __floats2half2_rn(v.x, v.y);
        __half2 h1 = __floats2half2_rn(v.z, v.w);
        uint2 u = make_uint2(*(uint32_t*)&h0, *(uint32_t*)&h1);
        ((uint2*)d)[i] = u;
    }
}
// out[t] = g_out2[2t] + g_out2[2t+1]  (vectorized)
__global__ void k_combine(float* __restrict__ out) {
    int i = blockIdx.x * blockDim.x + threadIdx.x;   // over T*H/4
    if (i < T_TOK * H_DIM / 4) {
        int t = i / (H_DIM / 4), j = i % (H_DIM / 4);
        const float4* r0 = (const float4*)g_out2 + (size_t)(2 * t)     * (H_DIM / 4) + j;
        const float4* r1 = (const float4*)g_out2 + (size_t)(2 * t + 1) * (H_DIM / 4) + j;
        float4 a = *r0, b = *r1;
        ((float4*)out)[i] = make_float4(a.x + b.x, a.y + b.y, a.z + b.z, a.w + b.w);
    }
}

// ================= GEMM1: hidden @ W1[e] + b1, swiglu -> g_interh =================
__global__ void __launch_bounds__(256, 2) k_gemm1(const float* __restrict__ bias)
{
    extern __shared__ char smem[];
    int tileIdx = blockIdx.y;
    if (tileIdx >= g_numTiles) return;
    int e = g_tileE[tileIdx], rowStart = g_tileRow[tileIdx];
    int rowsHere = min(BM, g_counts[e] - rowStart);
    int n0 = blockIdx.x * BN;
    int tid = threadIdx.x;

    int* sSlot = (int*)smem;
    if (tid < BM)
        sSlot[tid] = (tid < rowsHere) ? g_slots[e * TK + rowStart + tid]
                                      : g_slots[e * TK + rowStart];
    __syncthreads();

    // A loader: row = tid>>1, 2x cp16 covering 32 halfs
    int aldr = tid >> 1, asp = (tid & 1) * 16;
    const __half* aSrc = g_hidh + (size_t)(sSlot[aldr] >> 1) * H_DIM + asp;
    // B loader: k-row = tid>>3, 2x cp16 at cols (tid&7)*8 and +64
    int bldr = tid >> 3, bcol = (tid & 7) * 8;
    const __half* bSrc = g_w1h + (size_t)e * H_DIM * N1 + (size_t)bldr * N1 + n0 + bcol;

    uint32_t smU = smem_u32(smem);
    uint32_t aD = smU + AOFF + (aldr * ASTR + asp) * 2;
    uint32_t bD = smU + BOFF + (bldr * BSTR + bcol) * 2;

    int lane = tid & 31, g_ = lane >> 2, tq = lane & 3;
    int wid = tid >> 5;
    int wm = (wid >> 2) * 64, wn = (wid & 3) * 32;

    // LDSM lane addressing: t = lane>>3 (tile), rw = lane&7 (row in tile)
    int lt = lane >> 3, lrw = lane & 7;
    uint32_t aA[4], bA[2];
    #pragma unroll
    for (int mt = 0; mt < 4; mt++)
        aA[mt] = ((wm + mt * 16 + (lt & 1) * 8 + lrw) * ASTR + (lt >> 1) * 8) * 2;
    #pragma unroll
    for (int p = 0; p < 2; p++)
        bA[p] = (((lt & 1) * 8 + lrw) * BSTR + wn + p * 16 + (lt >> 1) * 8) * 2;

    float c[4][4][4];
    #pragma unroll
    for (int i = 0; i < 4; i++)
        #pragma unroll
        for (int j = 0; j < 4; j++)
            #pragma unroll
            for (int q = 0; q < 4; q++) c[i][j][q] = 0.0f;

#define ISSUE1(CH, ST) do {                          \
    int k0 = (CH) * KC;                              \
    uint32_t ad = aD + (ST) * (ABUF * 2);            \
    cp16(ad,      aSrc + k0);                        \
    cp16(ad + 16, aSrc + k0 + 8);                    \
    uint32_t bd = bD + (ST) * (BBUF * 2);            \
    const __half* bs = bSrc + (size_t)k0 * N1;       \
    cp16(bd,       bs);                              \
    cp16(bd + 128, bs + 64); } while (0)

    const int NC = H_DIM / KC;   // 32
    ISSUE1(0, 0); CP_COMMIT();
    ISSUE1(1, 1); CP_COMMIT();

    for (int ch = 0; ch < NC; ch++) {
        int st = ch & 3;
        if (ch + 2 < NC) { ISSUE1(ch + 2, (ch + 2) & 3); CP_COMMIT(); CP_WAIT(2); }
        else if (ch + 1 < NC) { CP_WAIT(1); }
        else { CP_WAIT(0); }
        __syncthreads();   // all warps' cp for stage ch complete before reads
        compute_chunk(smU + AOFF + st * (ABUF * 2), smU + BOFF + st * (BBUF * 2),
                      c, aA, bA);
        // no trailing barrier: 4 stages guarantee writer/reader separation
    }
#undef ISSUE1

    // epilogue: bias + swiglu, store fp16 to g_interh
    const float* bp = bias + (size_t)e * N1 + n0;
    #pragma unroll
    for (int mt = 0; mt < 4; mt++) {
        #pragma unroll
        for (int half = 0; half < 2; half++) {
            int r = wm + mt * 16 + g_ + half * 8;
            if (r < rowsHere) {
                int slot = sSlot[r];
                __half* orow = g_interh + (size_t)slot * F_DIM + (n0 >> 1) + (wn >> 1);
                #pragma unroll
                for (int nt = 0; nt < 4; nt++) {
                    int cb = wn + nt * 8 + 2 * tq;
                    float gt = c[mt][nt][half * 2 + 0] + bp[cb];
                    float up = c[mt][nt][half * 2 + 1] + bp[cb + 1];
                    gt = fminf(gt, 7.0f);
                    up = fminf(fmaxf(up, -7.0f), 7.0f);
                    float glu = gt / (1.0f + __expf(-1.702f * gt));
                    orow[nt * 4 + tq] = __float2half_rn((up + 1.0f) * glu);
                }
            }
        }
    }
}

// ================= GEMM2: g_interh @ W2[e] + b2 -> g_out2 (per-slot, weighted) =================
__global__ void __launch_bounds__(256, 2) k_gemm2(
    const float* __restrict__ bias, const float* __restrict__ tw)
{
    extern __shared__ char smem[];
    int tileIdx = blockIdx.y;
    if (tileIdx >= g_numTiles) return;
    int e = g_tileE[tileIdx], rowStart = g_tileRow[tileIdx];
    int rowsHere = min(BM, g_counts[e] - rowStart);
    int n0 = blockIdx.x * BN;
    int tid = threadIdx.x;

    int* sSlot = (int*)smem;
    if (tid < BM)
        sSlot[tid] = (tid < rowsHere) ? g_slots[e * TK + rowStart + tid]
                                      : g_slots[e * TK + rowStart];
    __syncthreads();

    int aldr = tid >> 1, asp = (tid & 1) * 16;
    const __half* aSrc = g_interh + (size_t)sSlot[aldr] * F_DIM + asp;
    int bldr = tid >> 3, bcol = (tid & 7) * 8;
    const __half* bSrc = g_w2h + (size_t)e * F_DIM * H_DIM + (size_t)bldr * H_DIM + n0 + bcol;

    uint32_t smU = smem_u32(smem);
    uint32_t aD = smU + AOFF + (aldr * ASTR + asp) * 2;
    uint32_t bD = smU + BOFF + (bldr * BSTR + bcol) * 2;

    int lane = tid & 31, g_ = lane >> 2, tq = lane & 3;
    int wid = tid >> 5;
    int wm = (wid >> 2) * 64, wn = (wid & 3) * 32;

    int lt = lane >> 3, lrw = lane & 7;
    uint32_t aA[4], bA[2];
    #pragma unroll
    for (int mt = 0; mt < 4; mt++)
        aA[mt] = ((wm + mt * 16 + (lt & 1) * 8 + lrw) * ASTR + (lt >> 1) * 8) * 2;
    #pragma unroll
    for (int p = 0; p < 2; p++)
        bA[p] = (((lt & 1) * 8 + lrw) * BSTR + wn + p * 16 + (lt >> 1) * 8) * 2;

    float c[4][4][4];
    #pragma unroll
    for (int i = 0; i < 4; i++)
        #pragma unroll
        for (int j = 0; j < 4; j++)
            #pragma unroll
            for (int q = 0; q < 4; q++) c[i][j][q] = 0.0f;

#define ISSUE2(CH, ST) do {                          \
    int k0 = (CH) * KC;                              \
    uint32_t ad = aD + (ST) * (ABUF * 2);            \
    cp16(ad,      aSrc + k0);                        \
    cp16(ad + 16, aSrc + k0 + 8);                    \
    uint32_t bd = bD + (ST) * (BBUF * 2);            \
    const __half* bs = bSrc + (size_t)k0 * H_DIM;    \
    cp16(bd,       bs);                              \
    cp16(bd + 128, bs + 64); } while (0)

    const int NC = F_DIM / KC;   // 64
    ISSUE2(0, 0); CP_COMMIT();
    ISSUE2(1, 1); CP_COMMIT();

    for (int ch = 0; ch < NC; ch++) {
        int st = ch & 3;
        if (ch + 2 < NC) { ISSUE2(ch + 2, (ch + 2) & 3); CP_COMMIT(); CP_WAIT(2); }
        else if (ch + 1 < NC) { CP_WAIT(1); }
        else { CP_WAIT(0); }
        __syncthreads();
        compute_chunk(smU + AOFF + st * (ABUF * 2), smU + BOFF + st * (BBUF * 2),
                      c, aA, bA);
    }
#undef ISSUE2

    // epilogue: bias, routing weight, plain stores to per-slot buffer
    const float* bp = bias + (size_t)e * H_DIM + n0;
    #pragma unroll
    for (int mt = 0; mt < 4; mt++) {
        #pragma unroll
        for (int half = 0; half < 2; half++) {
            int r = wm + mt * 16 + g_ + half * 8;
            if (r < rowsHere) {
                int slot = sSlot[r];
                float w = tw[slot];
                float* orow = g_out2 + (size_t)slot * H_DIM + n0 + wn;
                #pragma unroll
                for (int nt = 0; nt < 4; nt++) {
                    int cb = nt * 8 + 2 * tq;
                    float2 v = make_float2(w * (c[mt][nt][half * 2 + 0] + bp[wn + cb]),
                                           w * (c[mt][nt][half * 2 + 1] + bp[wn + cb + 1]));
                    *(float2*)(orow + cb) = v;
                }
            }
        }
    }
}

extern "C" void kernel_launch(void* const* d_in, const int* in_sizes, int n_in,
                              void* d_out, int out_size) {
    const float* hidden = (const float*)d_in[0];   // [T, H]
    const float* tw     = (const float*)d_in[1];   // [T, K]
    const int*   ids    = (const int*)d_in[2];     // [T, K]
    const float* w1     = (const float*)d_in[3];   // [E, H, 2F]
    const float* b1     = (const float*)d_in[4];   // [E, 2F]
    const float* w2     = (const float*)d_in[5];   // [E, F, H]
    const float* b2     = (const float*)d_in[6];   // [E, H]
    float* out = (float*)d_out;                    // [T, H]

    cudaFuncSetAttribute(k_gemm1, cudaFuncAttributeMaxDynamicSharedMemorySize, SMEM_BYTES);
    cudaFuncSetAttribute(k_gemm2, cudaFuncAttributeMaxDynamicSharedMemorySize, SMEM_BYTES);

    __half* d_w1h;  cudaGetSymbolAddress((void**)&d_w1h, g_w1h);
    __half* d_w2h;  cudaGetSymbolAddress((void**)&d_w2h, g_w2h);
    __half* d_hidh; cudaGetSymbolAddress((void**)&d_hidh, g_hidh);

    k_init<<<1, 32>>>();
    k_build<<<(TK + 255) / 256, 256>>>(ids);
    k_tilemap<<<1, 32>>>();
    // fp32 -> fp16 converts (ldmatrix.trans consumes B in native layout)
    k_cvt<<<(E_NUM * H_DIM * N1 / 4 + 255) / 256, 256>>>(w1, d_w1h, E_NUM * H_DIM * N1 / 4);
    k_cvt<<<(E_NUM * F_DIM * H_DIM / 4 + 255) / 256, 256>>>(w2, d_w2h, E_NUM * F_DIM * H_DIM / 4);
    k_cvt<<<(T_TOK * H_DIM / 4 + 255) / 256, 256>>>(hidden, d_hidh, T_TOK * H_DIM / 4);

    k_gemm1<<<dim3(N1 / BN, MAX_TILES), 256, SMEM_BYTES>>>(b1);
    k_gemm2<<<dim3(H_DIM / BN, MAX_TILES), 256, SMEM_BYTES>>>(b2, tw);
    k_combine<<<(T_TOK * H_DIM / 4 + 255) / 256, 256>>>(out);
}